// round 1
// baseline (speedup 1.0000x reference)
#include <cuda_runtime.h>
#include <cstdint>

// ---------------------------------------------------------------------------
// Quan_adder2d: fake-quant(x, 16b global) ; fake-quant(W, 8b per-out-channel)
// out[n,f,ho,wo] = -sum_{c,i,j} | qw[f,c,i,j] - qx[n,c,ho+i-1,wo+j-1] |
// x: (4,64,28,28) f32, W: (64,64,3,3) f32, out: (4,64,28,28) f32
// ---------------------------------------------------------------------------

#define N_BATCH 4
#define C_IN    64
#define HW      28
#define F_OUT   64
#define KDIM    576          // C_IN * 9
#define X_ELEMS (N_BATCH*C_IN*HW*HW)   // 200704
#define QX_MAX  65535.0f
#define QW_MAX  255.0f

// device scratch (no allocations allowed)
__device__ unsigned g_min_u;
__device__ unsigned g_max_u;
__device__ float    g_qw[KDIM * F_OUT];   // layout [k][f]

// order-preserving float<->uint transform (monotonic under unsigned compare)
__device__ __forceinline__ unsigned enc_f(float f) {
    int i = __float_as_int(f);
    return (i < 0) ? ~(unsigned)i : ((unsigned)i | 0x80000000u);
}
__device__ __forceinline__ float dec_f(unsigned u) {
    int i = (u & 0x80000000u) ? (int)(u & 0x7FFFFFFFu) : (int)(~u);
    return __int_as_float(i);
}

__global__ void k_init() {
    g_min_u = 0xFFFFFFFFu;
    g_max_u = 0u;
}

__global__ void k_minmax(const float* __restrict__ x, int n) {
    int idx    = blockIdx.x * blockDim.x + threadIdx.x;
    int stride = gridDim.x * blockDim.x;
    float mn =  1e30f, mx = -1e30f;
    for (int i = idx; i < n; i += stride) {
        float v = x[i];
        mn = fminf(mn, v);
        mx = fmaxf(mx, v);
    }
    #pragma unroll
    for (int o = 16; o > 0; o >>= 1) {
        mn = fminf(mn, __shfl_xor_sync(0xffffffffu, mn, o));
        mx = fmaxf(mx, __shfl_xor_sync(0xffffffffu, mx, o));
    }
    __shared__ float smn[8], smx[8];
    int warp = threadIdx.x >> 5, lane = threadIdx.x & 31;
    if (lane == 0) { smn[warp] = mn; smx[warp] = mx; }
    __syncthreads();
    if (threadIdx.x == 0) {
        int nw = (blockDim.x + 31) >> 5;
        for (int w = 1; w < nw; ++w) {
            mn = fminf(mn, smn[w]);
            mx = fmaxf(mx, smx[w]);
        }
        atomicMin(&g_min_u, enc_f(mn));
        atomicMax(&g_max_u, enc_f(mx));
    }
}

// one warp per output channel f: min/max over 576 vals, quantize, write [k][f]
__global__ void k_quantw(const float* __restrict__ W) {
    int warp = (blockIdx.x * blockDim.x + threadIdx.x) >> 5;
    int lane = threadIdx.x & 31;
    if (warp >= F_OUT) return;
    const float* wf = W + warp * KDIM;
    float v[18];
    float mn = 1e30f, mx = -1e30f;
    #pragma unroll
    for (int t = 0; t < 18; ++t) {       // 18*32 = 576
        v[t] = wf[lane + t * 32];
        mn = fminf(mn, v[t]);
        mx = fmaxf(mx, v[t]);
    }
    #pragma unroll
    for (int o = 16; o > 0; o >>= 1) {
        mn = fminf(mn, __shfl_xor_sync(0xffffffffu, mn, o));
        mx = fmaxf(mx, __shfl_xor_sync(0xffffffffu, mx, o));
    }
    float scale = fmaxf(__fdiv_rn(mx - mn, QW_MAX), 1e-12f);
    float zp    = rintf(__fdiv_rn(-mn, scale));
    #pragma unroll
    for (int t = 0; t < 18; ++t) {
        float q = fminf(fmaxf(rintf(__fdiv_rn(v[t], scale)) + zp, 0.0f), QW_MAX);
        g_qw[(lane + t * 32) * F_OUT + warp] = (q - zp) * scale;
    }
}

// main adder-conv. grid = (28 ho, 4 n), 224 threads, thread tile 4f x 2wo.
#define SW_FLOATS (KDIM * F_OUT)          // 36864
#define SX_FLOATS (C_IN * 3 * 30)         // 5760 : [c][row 3][col 30 padded]
#define SMEM_BYTES ((SW_FLOATS + SX_FLOATS) * 4)

__global__ void __launch_bounds__(224, 1) k_main(const float* __restrict__ x,
                                                 float* __restrict__ out) {
    const int ho = blockIdx.x;   // 0..27
    const int n  = blockIdx.y;   // 0..3
    extern __shared__ float smem[];
    float* sw = smem;             // [k][f]
    float* sx = smem + SW_FLOATS; // [c][3][30]

    const int tid = threadIdx.x;

    // activation quant params (g_min/g_max written by prior kernels)
    const float xmn    = dec_f(g_min_u);
    const float xmx    = dec_f(g_max_u);
    const float xscale = fmaxf(__fdiv_rn(xmx - xmn, QX_MAX), 1e-12f);
    const float xzp    = rintf(__fdiv_rn(-xmn, xscale));

    // stage full dequantized W tile (147KB) into smem
    const float4* gsrc = (const float4*)g_qw;
    float4*       sdst = (float4*)sw;
    for (int i = tid; i < SW_FLOATS / 4; i += 224) sdst[i] = gsrc[i];

    // stage 3 input rows (with zero padding), quantizing inline
    for (int idx = tid; idx < SX_FLOATS; idx += 224) {
        int c   = idx / 90;
        int rem = idx - c * 90;
        int r   = rem / 30;
        int col = rem - r * 30;
        int h   = ho + r - 1;
        int w   = col - 1;
        float v = 0.0f;
        if ((unsigned)h < (unsigned)HW && (unsigned)w < (unsigned)HW) {
            float xv = x[((n * C_IN + c) * HW + h) * HW + w];
            float q  = fminf(fmaxf(rintf(__fdiv_rn(xv, xscale)) + xzp, 0.0f), QX_MAX);
            v = (q - xzp) * xscale;
        }
        sx[idx] = v;
    }
    __syncthreads();

    const int fgrp = tid & 15;   // 0..15 -> f0 = 4*fgrp
    const int wog  = tid >> 4;   // 0..13 -> wo0 = 2*wog
    const int f0   = fgrp * 4;
    const int wo0  = wog * 2;

    float a00 = 0.f, a01 = 0.f, a10 = 0.f, a11 = 0.f;
    float a20 = 0.f, a21 = 0.f, a30 = 0.f, a31 = 0.f;

#define STEP(W4, XA, XB)                                        \
    a00 += fabsf((W4).x - (XA)); a01 += fabsf((W4).x - (XB));   \
    a10 += fabsf((W4).y - (XA)); a11 += fabsf((W4).y - (XB));   \
    a20 += fabsf((W4).z - (XA)); a21 += fabsf((W4).z - (XB));   \
    a30 += fabsf((W4).w - (XA)); a31 += fabsf((W4).w - (XB));

    #pragma unroll 2
    for (int c = 0; c < C_IN; ++c) {
        const float* xc = sx + c * 90 + wo0;
        const float* wc = sw + c * 9 * F_OUT + f0;
        #pragma unroll
        for (int i = 0; i < 3; ++i) {
            const float* xr = xc + i * 30;
            float x0 = xr[0], x1 = xr[1], x2 = xr[2], x3 = xr[3];
            const float* wr = wc + i * 3 * F_OUT;
            float4 w;
            w = *(const float4*)(wr);              STEP(w, x0, x1)
            w = *(const float4*)(wr + F_OUT);      STEP(w, x1, x2)
            w = *(const float4*)(wr + 2 * F_OUT);  STEP(w, x2, x3)
        }
    }
#undef STEP

    float* op = out + ((n * F_OUT + f0) * HW + ho) * HW + wo0;
    op[0] = -a00; op[1] = -a01; op += HW * HW;
    op[0] = -a10; op[1] = -a11; op += HW * HW;
    op[0] = -a20; op[1] = -a21; op += HW * HW;
    op[0] = -a30; op[1] = -a31;
}

extern "C" void kernel_launch(void* const* d_in, const int* in_sizes, int n_in,
                              void* d_out, int out_size) {
    const float* x = (const float*)d_in[0];
    const float* W = (const float*)d_in[1];
    float* out = (float*)d_out;

    cudaFuncSetAttribute(k_main, cudaFuncAttributeMaxDynamicSharedMemorySize,
                         SMEM_BYTES);

    k_init<<<1, 1>>>();
    k_minmax<<<98, 256>>>(x, X_ELEMS);
    k_quantw<<<2, 1024>>>(W);
    dim3 grid(HW, N_BATCH);
    k_main<<<grid, 224, SMEM_BYTES>>>(x, out);
}

// round 2
// speedup vs baseline: 1.0494x; 1.0494x over previous
#include <cuda_runtime.h>
#include <cstdint>

// ---------------------------------------------------------------------------
// Quan_adder2d: fake-quant(x, 16b global) ; fake-quant(W, 8b per-out-channel)
// out[n,f,ho,wo] = -sum_{c,i,j} | qw[f,c,i,j] - qx[n,c,ho+i-1,wo+j-1] |
// x: (4,64,28,28) f32, W: (64,64,3,3) f32, out: (4,64,28,28) f32
// ---------------------------------------------------------------------------

#define N_BATCH 4
#define C_IN    64
#define HW      28
#define F_OUT   64
#define KDIM    576
#define QX_MAX  65535.0f
#define QW_MAX  255.0f

#define MMB     64            // minmax blocks
#define SLICES  8
#define CPS     8             // channels per slice
#define TPS     112           // threads per slice (16 fgrp x 7 wog)
#define THREADS (SLICES*TPS)  // 896

typedef unsigned long long ull;

__device__ float g_bmin[MMB];
__device__ float g_bmax[MMB];
__device__ float g_qw[KDIM * F_OUT];   // layout [k][f]

// ---------------- packed f32x2 helpers ----------------
__device__ __forceinline__ ull add2(ull a, ull b) {
    ull r; asm("add.rn.f32x2 %0, %1, %2;" : "=l"(r) : "l"(a), "l"(b)); return r;
}
__device__ __forceinline__ ull abs2(ull a) { return a & 0x7fffffff7fffffffULL; }
__device__ __forceinline__ float lo2(ull a) { return __int_as_float((int)(unsigned)a); }
__device__ __forceinline__ float hi2(ull a) { return __int_as_float((int)(a >> 32)); }

// ---------------- x global min/max: one slot per block ----------------
__global__ void k_minmax(const float4* __restrict__ x, int n4) {
    int idx    = blockIdx.x * blockDim.x + threadIdx.x;
    int stride = gridDim.x * blockDim.x;
    float mn = 1e30f, mx = -1e30f;
    for (int i = idx; i < n4; i += stride) {
        float4 v = x[i];
        mn = fminf(fminf(fminf(mn, v.x), v.y), fminf(v.z, v.w));
        mx = fmaxf(fmaxf(fmaxf(mx, v.x), v.y), fmaxf(v.z, v.w));
    }
    #pragma unroll
    for (int o = 16; o > 0; o >>= 1) {
        mn = fminf(mn, __shfl_xor_sync(0xffffffffu, mn, o));
        mx = fmaxf(mx, __shfl_xor_sync(0xffffffffu, mx, o));
    }
    __shared__ float smn[8], smx[8];
    int warp = threadIdx.x >> 5, lane = threadIdx.x & 31;
    if (lane == 0) { smn[warp] = mn; smx[warp] = mx; }
    __syncthreads();
    if (threadIdx.x == 0) {
        int nw = blockDim.x >> 5;
        for (int w = 1; w < nw; ++w) {
            mn = fminf(mn, smn[w]);
            mx = fmaxf(mx, smx[w]);
        }
        g_bmin[blockIdx.x] = mn;
        g_bmax[blockIdx.x] = mx;
    }
}

// ---------------- per-channel W quant -> g_qw [k][f] ----------------
__global__ void k_quantw(const float* __restrict__ W) {
    int warp = (blockIdx.x * blockDim.x + threadIdx.x) >> 5;
    int lane = threadIdx.x & 31;
    if (warp >= F_OUT) return;
    const float* wf = W + warp * KDIM;
    float v[18];
    float mn = 1e30f, mx = -1e30f;
    #pragma unroll
    for (int t = 0; t < 18; ++t) {
        v[t] = wf[lane + t * 32];
        mn = fminf(mn, v[t]);
        mx = fmaxf(mx, v[t]);
    }
    #pragma unroll
    for (int o = 16; o > 0; o >>= 1) {
        mn = fminf(mn, __shfl_xor_sync(0xffffffffu, mn, o));
        mx = fmaxf(mx, __shfl_xor_sync(0xffffffffu, mx, o));
    }
    float scale = fmaxf(__fdiv_rn(mx - mn, QW_MAX), 1e-12f);
    float zp    = rintf(__fdiv_rn(-mn, scale));
    #pragma unroll
    for (int t = 0; t < 18; ++t) {
        float q = fminf(fmaxf(rintf(__fdiv_rn(v[t], scale)) + zp, 0.0f), QW_MAX);
        g_qw[(lane + t * 32) * F_OUT + warp] = (q - zp) * scale;
    }
}

// ---------------- main adder-conv ----------------
// grid (28 ho, 4 n), 896 threads = 8 c-slices x (16 fgrp x 7 wog)
// smem: W [576][64] (147456B) + x dup-neg [64][3][30]x2 (46080B) + red (28672B)
#define SW_FLOATS  (KDIM * F_OUT)       // 36864
#define SX_PAIRS   (C_IN * 3 * 30)      // 5760 float2 (negated, duplicated)
#define RED_F4     (4 * TPS * 4)        // 1792 float4
#define SMEM_BYTES (SW_FLOATS*4 + SX_PAIRS*8 + RED_F4*16)   // 222208

__global__ void __launch_bounds__(THREADS, 1) k_main(const float* __restrict__ x,
                                                     float* __restrict__ out) {
    const int ho  = blockIdx.x;
    const int n   = blockIdx.y;
    const int tid = threadIdx.x;

    extern __shared__ float smem[];
    float*  sw   = smem;
    float2* sx   = (float2*)(smem + SW_FLOATS);
    float4* red  = (float4*)(smem + SW_FLOATS + SX_PAIRS * 2);

    // activation quant params (redundant per-thread reduce over 64 slots)
    float xmn = 1e30f, xmx = -1e30f;
    #pragma unroll 8
    for (int i = 0; i < MMB; ++i) {
        xmn = fminf(xmn, g_bmin[i]);
        xmx = fmaxf(xmx, g_bmax[i]);
    }
    const float xscale = fmaxf(__fdiv_rn(xmx - xmn, QX_MAX), 1e-12f);
    const float xzp    = rintf(__fdiv_rn(-xmn, xscale));

    // stage W (dequantized, [k][f])
    {
        const float4* gsrc = (const float4*)g_qw;
        float4*       sdst = (float4*)sw;
        for (int i = tid; i < SW_FLOATS / 4; i += THREADS) sdst[i] = gsrc[i];
    }
    // stage x: 3 rows, quantize, NEGATE, DUPLICATE
    for (int idx = tid; idx < SX_PAIRS; idx += THREADS) {
        int c   = idx / 90;
        int rem = idx - c * 90;
        int r   = rem / 30;
        int col = rem - r * 30;
        int h   = ho + r - 1;
        int w   = col - 1;
        float v = 0.0f;
        if ((unsigned)h < (unsigned)HW && (unsigned)w < (unsigned)HW) {
            float xv = x[((n * C_IN + c) * HW + h) * HW + w];
            float q  = fminf(fmaxf(rintf(__fdiv_rn(xv, xscale)) + xzp, 0.0f), QX_MAX);
            v = (q - xzp) * xscale;
        }
        sx[idx] = make_float2(-v, -v);
    }
    __syncthreads();

    const int slice = tid / TPS;          // 0..7
    const int t     = tid - slice * TPS;  // 0..111
    const int fgrp  = t & 15;             // f0 = 4*fgrp
    const int wog   = t >> 4;             // 0..6, wo0 = 4*wog
    const int f0    = fgrp * 4;
    const int wo0   = wog * 4;
    const int c0    = slice * CPS;

    ull acc[2][4];
    #pragma unroll
    for (int p = 0; p < 2; ++p)
        #pragma unroll
        for (int k = 0; k < 4; ++k) acc[p][k] = 0ULL;

    for (int cc = 0; cc < CPS; ++cc) {
        const int c = c0 + cc;
        const float2* xc = sx + c * 90 + wo0;
        const float*  wc = sw + c * 9 * F_OUT + f0;
        #pragma unroll
        for (int i = 0; i < 3; ++i) {
            ull nx[6];
            #pragma unroll
            for (int k = 0; k < 6; ++k)
                nx[k] = *(const ull*)(xc + i * 30 + k);
            ull wp[3][2];
            #pragma unroll
            for (int j = 0; j < 3; ++j) {
                ulonglong2 w2 = *(const ulonglong2*)(wc + (i * 3 + j) * F_OUT);
                wp[j][0] = w2.x;
                wp[j][1] = w2.y;
            }
            #pragma unroll
            for (int j = 0; j < 3; ++j)
                #pragma unroll
                for (int k = 0; k < 4; ++k) {
                    ull xd = nx[j + k];
                    acc[0][k] = add2(acc[0][k], abs2(add2(wp[j][0], xd)));
                    acc[1][k] = add2(acc[1][k], abs2(add2(wp[j][1], xd)));
                }
        }
    }

    // unpack: va[fl] = wo-vector (4 floats) for f = f0 + fl
    float4 va[4];
    va[0] = make_float4(lo2(acc[0][0]), lo2(acc[0][1]), lo2(acc[0][2]), lo2(acc[0][3]));
    va[1] = make_float4(hi2(acc[0][0]), hi2(acc[0][1]), hi2(acc[0][2]), hi2(acc[0][3]));
    va[2] = make_float4(lo2(acc[1][0]), lo2(acc[1][1]), lo2(acc[1][2]), lo2(acc[1][3]));
    va[3] = make_float4(hi2(acc[1][0]), hi2(acc[1][1]), hi2(acc[1][2]), hi2(acc[1][3]));

#define RSLOT(s, fl) red[(((s) * TPS + t) << 2) + (fl)]
#define RADD(s)                                                   \
    { _Pragma("unroll") for (int fl = 0; fl < 4; ++fl) {          \
        float4 o = RSLOT(s, fl);                                  \
        va[fl].x += o.x; va[fl].y += o.y;                         \
        va[fl].z += o.z; va[fl].w += o.w; } }
#define RSTORE(s)                                                 \
    { _Pragma("unroll") for (int fl = 0; fl < 4; ++fl) RSLOT(s, fl) = va[fl]; }

    // 8 -> 4
    if (slice >= 4) RSTORE(slice - 4);
    __syncthreads();
    if (slice < 4)  RADD(slice);
    __syncthreads();
    // 4 -> 2
    if (slice == 2 || slice == 3) RSTORE(slice - 2);
    __syncthreads();
    if (slice < 2)  RADD(slice);
    __syncthreads();
    // 2 -> 1
    if (slice == 1) RSTORE(0);
    __syncthreads();
    if (slice == 0) {
        RADD(0);
        float* op = out + ((n * F_OUT + f0) * HW + ho) * HW + wo0;
        #pragma unroll
        for (int fl = 0; fl < 4; ++fl) {
            float4 v = va[fl];
            *(float4*)(op + fl * HW * HW) = make_float4(-v.x, -v.y, -v.z, -v.w);
        }
    }
#undef RSLOT
#undef RADD
#undef RSTORE
}

extern "C" void kernel_launch(void* const* d_in, const int* in_sizes, int n_in,
                              void* d_out, int out_size) {
    const float* x = (const float*)d_in[0];
    const float* W = (const float*)d_in[1];
    float* out = (float*)d_out;

    cudaFuncSetAttribute(k_main, cudaFuncAttributeMaxDynamicSharedMemorySize,
                         SMEM_BYTES);

    k_minmax<<<MMB, 256>>>((const float4*)x, (N_BATCH * C_IN * HW * HW) / 4);
    k_quantw<<<2, 1024>>>(W);
    dim3 grid(HW, N_BATCH);
    k_main<<<grid, THREADS, SMEM_BYTES>>>(x, out);
}

// round 3
// speedup vs baseline: 1.1040x; 1.0520x over previous
#include <cuda_runtime.h>
#include <cstdint>

// ---------------------------------------------------------------------------
// Quan_adder2d: fake-quant(x, 16b global) ; fake-quant(W, 8b per-out-channel)
// out[n,f,ho,wo] = -sum_{c,i,j} | qw[f,c,i,j] - qx[n,c,ho+i-1,wo+j-1] |
// x: (4,64,28,28) f32, W: (64,64,3,3) f32, out: (4,64,28,28) f32
// ---------------------------------------------------------------------------

#define N_BATCH 4
#define C_IN    64
#define HW      28
#define F_OUT   64
#define KDIM    576
#define QX_MAX  65535.0f
#define QW_MAX  255.0f

#define MMB     128           // minmax blocks
#define SLICES  4
#define CPS     16            // channels per slice
#define TPS     112           // threads per slice (16 fgrp x 7 wog)
#define THREADS (SLICES*TPS)  // 448

typedef unsigned long long ull;

__device__ float g_bmin[MMB];
__device__ float g_bmax[MMB];
__device__ float g_xscale;
__device__ float g_xzp;
__device__ float g_qw[KDIM * F_OUT];   // layout [k][f]

// ---------------- packed f32x2 helpers ----------------
__device__ __forceinline__ ull add2(ull a, ull b) {
    ull r; asm("add.rn.f32x2 %0, %1, %2;" : "=l"(r) : "l"(a), "l"(b)); return r;
}
__device__ __forceinline__ ull abs2(ull a) { return a & 0x7fffffff7fffffffULL; }
__device__ __forceinline__ float lo2(ull a) { return __int_as_float((int)(unsigned)a); }
__device__ __forceinline__ float hi2(ull a) { return __int_as_float((int)(a >> 32)); }

// ---------------- x global min/max: one slot per block ----------------
__global__ void k_minmax(const float4* __restrict__ x, int n4) {
    int idx    = blockIdx.x * blockDim.x + threadIdx.x;
    int stride = gridDim.x * blockDim.x;
    float mn = 1e30f, mx = -1e30f;
    for (int i = idx; i < n4; i += stride) {
        float4 v = x[i];
        mn = fminf(fminf(fminf(mn, v.x), v.y), fminf(v.z, v.w));
        mx = fmaxf(fmaxf(fmaxf(mx, v.x), v.y), fmaxf(v.z, v.w));
    }
    #pragma unroll
    for (int o = 16; o > 0; o >>= 1) {
        mn = fminf(mn, __shfl_xor_sync(0xffffffffu, mn, o));
        mx = fmaxf(mx, __shfl_xor_sync(0xffffffffu, mx, o));
    }
    __shared__ float smn[8], smx[8];
    int warp = threadIdx.x >> 5, lane = threadIdx.x & 31;
    if (lane == 0) { smn[warp] = mn; smx[warp] = mx; }
    __syncthreads();
    if (threadIdx.x == 0) {
        int nw = blockDim.x >> 5;
        for (int w = 1; w < nw; ++w) {
            mn = fminf(mn, smn[w]);
            mx = fmaxf(mx, smx[w]);
        }
        g_bmin[blockIdx.x] = mn;
        g_bmax[blockIdx.x] = mx;
    }
}

// ---------------- W quant (blocks 0,1) + x-param finalize (block 2) --------
__global__ void k_quantw(const float* __restrict__ W) {
    if (blockIdx.x == 2) {
        // finalize activation quant params from the 128 block slots
        int t = threadIdx.x;
        if (t < 128) {
            float mn = g_bmin[t];
            float mx = g_bmax[t];
            #pragma unroll
            for (int o = 16; o > 0; o >>= 1) {
                mn = fminf(mn, __shfl_xor_sync(0xffffffffu, mn, o));
                mx = fmaxf(mx, __shfl_xor_sync(0xffffffffu, mx, o));
            }
            __shared__ float smn[4], smx[4];
            int warp = t >> 5, lane = t & 31;
            if (lane == 0) { smn[warp] = mn; smx[warp] = mx; }
            __syncthreads();
            if (t == 0) {
                for (int w = 1; w < 4; ++w) {
                    mn = fminf(mn, smn[w]);
                    mx = fmaxf(mx, smx[w]);
                }
                float scale = fmaxf(__fdiv_rn(mx - mn, QX_MAX), 1e-12f);
                g_xscale = scale;
                g_xzp    = rintf(__fdiv_rn(-mn, scale));
            }
        }
        return;
    }
    int warp = (blockIdx.x * blockDim.x + threadIdx.x) >> 5;
    int lane = threadIdx.x & 31;
    if (warp >= F_OUT) return;
    const float* wf = W + warp * KDIM;
    float v[18];
    float mn = 1e30f, mx = -1e30f;
    #pragma unroll
    for (int t = 0; t < 18; ++t) {
        v[t] = wf[lane + t * 32];
        mn = fminf(mn, v[t]);
        mx = fmaxf(mx, v[t]);
    }
    #pragma unroll
    for (int o = 16; o > 0; o >>= 1) {
        mn = fminf(mn, __shfl_xor_sync(0xffffffffu, mn, o));
        mx = fmaxf(mx, __shfl_xor_sync(0xffffffffu, mx, o));
    }
    float scale = fmaxf(__fdiv_rn(mx - mn, QW_MAX), 1e-12f);
    float zp    = rintf(__fdiv_rn(-mn, scale));
    #pragma unroll
    for (int t = 0; t < 18; ++t) {
        float q = fminf(fmaxf(rintf(__fdiv_rn(v[t], scale)) + zp, 0.0f), QW_MAX);
        g_qw[(lane + t * 32) * F_OUT + warp] = (q - zp) * scale;
    }
}

// ---------------- main adder-conv ----------------
// grid (28 ho, 4 n), 448 threads = 4 c-slices x (16 fgrp x 7 wog)
// smem: W [576][64] (147456B) + x dup-neg [64][3][30]x2 (46080B) + red (14336B)
#define SW_FLOATS  (KDIM * F_OUT)       // 36864
#define SX_PAIRS   (C_IN * 3 * 30)      // 5760 float2 (negated, duplicated)
#define RED_F4     (2 * TPS * 4)        // 896 float4
#define SMEM_BYTES (SW_FLOATS*4 + SX_PAIRS*8 + RED_F4*16)   // 207872

__global__ void __launch_bounds__(THREADS, 1) k_main(const float* __restrict__ x,
                                                     float* __restrict__ out) {
    const int ho  = blockIdx.x;
    const int n   = blockIdx.y;
    const int tid = threadIdx.x;

    extern __shared__ float smem[];
    float*  sw   = smem;
    float2* sx   = (float2*)(smem + SW_FLOATS);
    float4* red  = (float4*)(smem + SW_FLOATS + SX_PAIRS * 2);

    const float xscale = g_xscale;
    const float xzp    = g_xzp;

    // stage W (dequantized, [k][f])
    {
        const float4* gsrc = (const float4*)g_qw;
        float4*       sdst = (float4*)sw;
        for (int i = tid; i < SW_FLOATS / 4; i += THREADS) sdst[i] = gsrc[i];
    }
    // stage x: 3 rows, quantize, NEGATE, DUPLICATE
    for (int idx = tid; idx < SX_PAIRS; idx += THREADS) {
        int c   = idx / 90;
        int rem = idx - c * 90;
        int r   = rem / 30;
        int col = rem - r * 30;
        int h   = ho + r - 1;
        int w   = col - 1;
        float v = 0.0f;
        if ((unsigned)h < (unsigned)HW && (unsigned)w < (unsigned)HW) {
            float xv = x[((n * C_IN + c) * HW + h) * HW + w];
            float q  = fminf(fmaxf(rintf(__fdiv_rn(xv, xscale)) + xzp, 0.0f), QX_MAX);
            v = (q - xzp) * xscale;
        }
        sx[idx] = make_float2(-v, -v);
    }
    __syncthreads();

    const int slice = tid / TPS;          // 0..3
    const int t     = tid - slice * TPS;  // 0..111
    const int fgrp  = t & 15;             // f0 = 4*fgrp
    const int wog   = t >> 4;             // 0..6, wo0 = 4*wog
    const int f0    = fgrp * 4;
    const int wo0   = wog * 4;
    const int c0    = slice * CPS;

    ull acc[2][4];
    #pragma unroll
    for (int p = 0; p < 2; ++p)
        #pragma unroll
        for (int k = 0; k < 4; ++k) acc[p][k] = 0ULL;

    for (int cc = 0; cc < CPS; ++cc) {
        const int c = c0 + cc;
        const float2* xc = sx + c * 90 + wo0;
        const float*  wc = sw + c * 9 * F_OUT + f0;
        #pragma unroll
        for (int i = 0; i < 3; ++i) {
            // x window: 6 dup-pairs, loaded as 3 x 16B (wo0 even -> aligned)
            ulonglong2 xv0 = *(const ulonglong2*)(xc + i * 30);
            ulonglong2 xv1 = *(const ulonglong2*)(xc + i * 30 + 2);
            ulonglong2 xv2 = *(const ulonglong2*)(xc + i * 30 + 4);
            ull nx[6] = { xv0.x, xv0.y, xv1.x, xv1.y, xv2.x, xv2.y };
            #pragma unroll
            for (int j = 0; j < 3; ++j) {
                ulonglong2 w2 = *(const ulonglong2*)(wc + (i * 3 + j) * F_OUT);
                #pragma unroll
                for (int k = 0; k < 4; ++k) {
                    ull xd = nx[j + k];
                    acc[0][k] = add2(acc[0][k], abs2(add2(w2.x, xd)));
                    acc[1][k] = add2(acc[1][k], abs2(add2(w2.y, xd)));
                }
            }
        }
    }

    // unpack: va[fl] = wo-vector (4 floats) for f = f0 + fl
    float4 va[4];
    va[0] = make_float4(lo2(acc[0][0]), lo2(acc[0][1]), lo2(acc[0][2]), lo2(acc[0][3]));
    va[1] = make_float4(hi2(acc[0][0]), hi2(acc[0][1]), hi2(acc[0][2]), hi2(acc[0][3]));
    va[2] = make_float4(lo2(acc[1][0]), lo2(acc[1][1]), lo2(acc[1][2]), lo2(acc[1][3]));
    va[3] = make_float4(hi2(acc[1][0]), hi2(acc[1][1]), hi2(acc[1][2]), hi2(acc[1][3]));

#define RSLOT(s, fl) red[(((s) * TPS + t) << 2) + (fl)]
#define RADD(s)                                                   \
    { _Pragma("unroll") for (int fl = 0; fl < 4; ++fl) {          \
        float4 o = RSLOT(s, fl);                                  \
        va[fl].x += o.x; va[fl].y += o.y;                         \
        va[fl].z += o.z; va[fl].w += o.w; } }
#define RSTORE(s)                                                 \
    { _Pragma("unroll") for (int fl = 0; fl < 4; ++fl) RSLOT(s, fl) = va[fl]; }

    // 4 -> 2
    if (slice >= 2) RSTORE(slice - 2);
    __syncthreads();
    if (slice < 2)  RADD(slice);
    __syncthreads();
    // 2 -> 1
    if (slice == 1) RSTORE(0);
    __syncthreads();
    if (slice == 0) {
        RADD(0);
        float* op = out + ((n * F_OUT + f0) * HW + ho) * HW + wo0;
        #pragma unroll
        for (int fl = 0; fl < 4; ++fl) {
            float4 v = va[fl];
            *(float4*)(op + fl * HW * HW) = make_float4(-v.x, -v.y, -v.z, -v.w);
        }
    }
#undef RSLOT
#undef RADD
#undef RSTORE
}

extern "C" void kernel_launch(void* const* d_in, const int* in_sizes, int n_in,
                              void* d_out, int out_size) {
    const float* x = (const float*)d_in[0];
    const float* W = (const float*)d_in[1];
    float* out = (float*)d_out;

    cudaFuncSetAttribute(k_main, cudaFuncAttributeMaxDynamicSharedMemorySize,
                         SMEM_BYTES);

    k_minmax<<<MMB, 256>>>((const float4*)x, (N_BATCH * C_IN * HW * HW) / 4);
    k_quantw<<<3, 1024>>>(W);
    dim3 grid(HW, N_BATCH);
    k_main<<<grid, THREADS, SMEM_BYTES>>>(x, out);
}

// round 4
// speedup vs baseline: 1.3924x; 1.2613x over previous
#include <cuda_runtime.h>
#include <cstdint>

// ---------------------------------------------------------------------------
// Quan_adder2d: fake-quant(x, 16b global) ; fake-quant(W, 8b per-out-channel)
// out[n,f,ho,wo] = -sum_{c,i,j} | qw[f,c,i,j] - qx[n,c,ho+i-1,wo+j-1] |
// x: (4,64,28,28) f32, W: (64,64,3,3) f32, out: (4,64,28,28) f32
// ---------------------------------------------------------------------------

#define N_BATCH 4
#define C_IN    64
#define HW      28
#define F_OUT   64
#define KDIM    576
#define QX_MAX  65535.0f
#define QW_MAX  255.0f

#define MMB     32            // minmax partial slots
#define SLICES  4
#define CPS     16            // channels per slice
#define TPS     112           // threads per slice (16 fgrp x 7 wog)
#define THREADS (SLICES*TPS)  // 448

typedef unsigned long long ull;

__device__ float g_bmin[MMB];
__device__ float g_bmax[MMB];
__device__ float g_qw[KDIM * F_OUT];   // layout [k][f]

// ---------------- packed f32x2 helpers ----------------
__device__ __forceinline__ ull add2(ull a, ull b) {
    ull r; asm("add.rn.f32x2 %0, %1, %2;" : "=l"(r) : "l"(a), "l"(b)); return r;
}
__device__ __forceinline__ ull abs2(ull a) { return a & 0x7fffffff7fffffffULL; }
__device__ __forceinline__ float lo2(ull a) { return __int_as_float((int)(unsigned)a); }
__device__ __forceinline__ float hi2(ull a) { return __int_as_float((int)(a >> 32)); }

// ---------------------------------------------------------------------------
// k_prep: blocks 0,1 -> W quant (32 f each, coalesced transpose write)
//         blocks 2..33 -> x min/max partials (one slot per block)
// ---------------------------------------------------------------------------
#define PREP_SMEM (32 * 577 * 4)   // 73856 B

__global__ void __launch_bounds__(1024, 1) k_prep(const float* __restrict__ W,
                                                  const float4* __restrict__ x,
                                                  int n4) {
    extern __shared__ float sq[];   // [32][577]
    const int tid = threadIdx.x;

    if (blockIdx.x >= 2) {
        // ---- x global min/max ----
        int bid    = blockIdx.x - 2;
        int idx    = bid * 1024 + tid;
        int stride = MMB * 1024;
        float mn = 1e30f, mx = -1e30f;
        for (int i = idx; i < n4; i += stride) {
            float4 v = x[i];
            mn = fminf(fminf(fminf(mn, v.x), v.y), fminf(v.z, v.w));
            mx = fmaxf(fmaxf(fmaxf(mx, v.x), v.y), fmaxf(v.z, v.w));
        }
        #pragma unroll
        for (int o = 16; o > 0; o >>= 1) {
            mn = fminf(mn, __shfl_xor_sync(0xffffffffu, mn, o));
            mx = fmaxf(mx, __shfl_xor_sync(0xffffffffu, mx, o));
        }
        __shared__ float smn[32], smx[32];
        int warp = tid >> 5, lane = tid & 31;
        if (lane == 0) { smn[warp] = mn; smx[warp] = mx; }
        __syncthreads();
        if (warp == 0) {
            mn = smn[lane];
            mx = smx[lane];
            #pragma unroll
            for (int o = 16; o > 0; o >>= 1) {
                mn = fminf(mn, __shfl_xor_sync(0xffffffffu, mn, o));
                mx = fmaxf(mx, __shfl_xor_sync(0xffffffffu, mx, o));
            }
            if (lane == 0) { g_bmin[bid] = mn; g_bmax[bid] = mx; }
        }
        return;
    }

    // ---- W quant: this block handles f = blockIdx.x*32 .. +31 ----
    const int warp = tid >> 5;      // 0..31 -> local f
    const int lane = tid & 31;
    const int f    = blockIdx.x * 32 + warp;

    const float* wf = W + f * KDIM;
    float v[18];
    float mn = 1e30f, mx = -1e30f;
    #pragma unroll
    for (int t = 0; t < 18; ++t) {           // 18*32 = 576
        v[t] = wf[lane + t * 32];
        mn = fminf(mn, v[t]);
        mx = fmaxf(mx, v[t]);
    }
    #pragma unroll
    for (int o = 16; o > 0; o >>= 1) {
        mn = fminf(mn, __shfl_xor_sync(0xffffffffu, mn, o));
        mx = fmaxf(mx, __shfl_xor_sync(0xffffffffu, mx, o));
    }
    float scale = fmaxf(__fdiv_rn(mx - mn, QW_MAX), 1e-12f);
    float zp    = rintf(__fdiv_rn(-mn, scale));
    #pragma unroll
    for (int t = 0; t < 18; ++t) {
        float q = fminf(fmaxf(rintf(__fdiv_rn(v[t], scale)) + zp, 0.0f), QW_MAX);
        sq[warp * 577 + lane + t * 32] = (q - zp) * scale;   // row f, col k
    }
    __syncthreads();

    // transposed write: g_qw[k][f] with contiguous 128B stores
    const int j  = tid & 31;        // f-lane
    const int kk = tid >> 5;        // 0..31
    const int f0 = blockIdx.x * 32;
    #pragma unroll
    for (int p = 0; p < 18; ++p) {
        int k = p * 32 + kk;
        g_qw[k * F_OUT + f0 + j] = sq[j * 577 + k];
    }
}

// ---------------------------------------------------------------------------
// k_main: adder-conv. grid (28 ho, 4 n), 448 threads = 4 c-slices x 112
// smem: W [576][64] + x dup-neg [64][3][30]x2 + reduction + 2 quant params
// ---------------------------------------------------------------------------
#define SW_FLOATS  (KDIM * F_OUT)       // 36864
#define SX_PAIRS   (C_IN * 3 * 30)      // 5760 float2 (negated, duplicated)
#define RED_F4     (2 * TPS * 4)        // 896 float4
#define SMEM_BYTES (SW_FLOATS*4 + SX_PAIRS*8 + RED_F4*16 + 16)

__global__ void __launch_bounds__(THREADS, 1) k_main(const float* __restrict__ x,
                                                     float* __restrict__ out) {
    const int ho  = blockIdx.x;
    const int n   = blockIdx.y;
    const int tid = threadIdx.x;

    extern __shared__ float smem[];
    float*  sw   = smem;
    float2* sx   = (float2*)(smem + SW_FLOATS);
    float4* red  = (float4*)(smem + SW_FLOATS + SX_PAIRS * 2);
    float*  sprm = (float*)(red + RED_F4);

    // warp 0: finalize activation quant params from 32 partials
    if (tid < 32) {
        float mn = g_bmin[tid];
        float mx = g_bmax[tid];
        #pragma unroll
        for (int o = 16; o > 0; o >>= 1) {
            mn = fminf(mn, __shfl_xor_sync(0xffffffffu, mn, o));
            mx = fmaxf(mx, __shfl_xor_sync(0xffffffffu, mx, o));
        }
        if (tid == 0) {
            float scale = fmaxf(__fdiv_rn(mx - mn, QX_MAX), 1e-12f);
            sprm[0] = scale;
            sprm[1] = rintf(__fdiv_rn(-mn, scale));
        }
    }

    // stage W (dequantized, [k][f])
    {
        const float4* gsrc = (const float4*)g_qw;
        float4*       sdst = (float4*)sw;
        for (int i = tid; i < SW_FLOATS / 4; i += THREADS) sdst[i] = gsrc[i];
    }
    __syncthreads();

    const float xscale = sprm[0];
    const float xzp    = sprm[1];

    // stage x: 3 rows, quantize, NEGATE, DUPLICATE
    for (int idx = tid; idx < SX_PAIRS; idx += THREADS) {
        int c   = idx / 90;
        int rem = idx - c * 90;
        int r   = rem / 30;
        int col = rem - r * 30;
        int h   = ho + r - 1;
        int w   = col - 1;
        float v = 0.0f;
        if ((unsigned)h < (unsigned)HW && (unsigned)w < (unsigned)HW) {
            float xv = x[((n * C_IN + c) * HW + h) * HW + w];
            float q  = fminf(fmaxf(rintf(__fdiv_rn(xv, xscale)) + xzp, 0.0f), QX_MAX);
            v = (q - xzp) * xscale;
        }
        sx[idx] = make_float2(-v, -v);
    }
    __syncthreads();

    const int slice = tid / TPS;          // 0..3
    const int t     = tid - slice * TPS;  // 0..111
    const int fgrp  = t & 15;             // f0 = 4*fgrp
    const int wog   = t >> 4;             // 0..6, wo0 = 4*wog
    const int f0    = fgrp * 4;
    const int wo0   = wog * 4;
    const int c0    = slice * CPS;

    ull acc[2][4];
    #pragma unroll
    for (int p = 0; p < 2; ++p)
        #pragma unroll
        for (int k = 0; k < 4; ++k) acc[p][k] = 0ULL;

    const float2* xc = sx + c0 * 90 + wo0;
    const float*  wc = sw + c0 * 9 * F_OUT + f0;

    #pragma unroll 2
    for (int cc = 0; cc < CPS; ++cc) {
        #pragma unroll
        for (int i = 0; i < 3; ++i) {
            ulonglong2 xv0 = *(const ulonglong2*)(xc + i * 30);
            ulonglong2 xv1 = *(const ulonglong2*)(xc + i * 30 + 2);
            ulonglong2 xv2 = *(const ulonglong2*)(xc + i * 30 + 4);
            ull nx[6] = { xv0.x, xv0.y, xv1.x, xv1.y, xv2.x, xv2.y };
            #pragma unroll
            for (int j = 0; j < 3; ++j) {
                ulonglong2 w2 = *(const ulonglong2*)(wc + (i * 3 + j) * F_OUT);
                #pragma unroll
                for (int k = 0; k < 4; ++k) {
                    ull xd = nx[j + k];
                    acc[0][k] = add2(acc[0][k], abs2(add2(w2.x, xd)));
                    acc[1][k] = add2(acc[1][k], abs2(add2(w2.y, xd)));
                }
            }
        }
        xc += 90;
        wc += 9 * F_OUT;
    }

    // unpack: va[fl] = wo-vector (4 floats) for f = f0 + fl
    float4 va[4];
    va[0] = make_float4(lo2(acc[0][0]), lo2(acc[0][1]), lo2(acc[0][2]), lo2(acc[0][3]));
    va[1] = make_float4(hi2(acc[0][0]), hi2(acc[0][1]), hi2(acc[0][2]), hi2(acc[0][3]));
    va[2] = make_float4(lo2(acc[1][0]), lo2(acc[1][1]), lo2(acc[1][2]), lo2(acc[1][3]));
    va[3] = make_float4(hi2(acc[1][0]), hi2(acc[1][1]), hi2(acc[1][2]), hi2(acc[1][3]));

#define RSLOT(s, fl) red[(((s) * TPS + t) << 2) + (fl)]
#define RADD(s)                                                   \
    { _Pragma("unroll") for (int fl = 0; fl < 4; ++fl) {          \
        float4 o = RSLOT(s, fl);                                  \
        va[fl].x += o.x; va[fl].y += o.y;                         \
        va[fl].z += o.z; va[fl].w += o.w; } }
#define RSTORE(s)                                                 \
    { _Pragma("unroll") for (int fl = 0; fl < 4; ++fl) RSLOT(s, fl) = va[fl]; }

    // 4 -> 2
    if (slice >= 2) RSTORE(slice - 2);
    __syncthreads();
    if (slice < 2)  RADD(slice);
    __syncthreads();
    // 2 -> 1
    if (slice == 1) RSTORE(0);
    __syncthreads();
    if (slice == 0) {
        RADD(0);
        float* op = out + ((n * F_OUT + f0) * HW + ho) * HW + wo0;
        #pragma unroll
        for (int fl = 0; fl < 4; ++fl) {
            float4 v = va[fl];
            *(float4*)(op + fl * HW * HW) = make_float4(-v.x, -v.y, -v.z, -v.w);
        }
    }
#undef RSLOT
#undef RADD
#undef RSTORE
}

extern "C" void kernel_launch(void* const* d_in, const int* in_sizes, int n_in,
                              void* d_out, int out_size) {
    const float* x = (const float*)d_in[0];
    const float* W = (const float*)d_in[1];
    float* out = (float*)d_out;

    cudaFuncSetAttribute(k_prep, cudaFuncAttributeMaxDynamicSharedMemorySize,
                         PREP_SMEM);
    cudaFuncSetAttribute(k_main, cudaFuncAttributeMaxDynamicSharedMemorySize,
                         SMEM_BYTES);

    k_prep<<<MMB + 2, 1024, PREP_SMEM>>>(W, (const float4*)x,
                                         (N_BATCH * C_IN * HW * HW) / 4);
    dim3 grid(HW, N_BATCH);
    k_main<<<grid, THREADS, SMEM_BYTES>>>(x, out);
}

// round 5
// speedup vs baseline: 1.6275x; 1.1689x over previous
#include <cuda_runtime.h>
#include <cstdint>

// ---------------------------------------------------------------------------
// Quan_adder2d: fake-quant(x, 16b global) ; fake-quant(W, 8b per-out-channel)
// out[n,f,ho,wo] = -sum_{c,i,j} | qw[f,c,i,j] - qx[n,c,ho+i-1,wo+j-1] |
// Strategy: re-grid qw onto the global 16-bit x grid ->
//   |qw - qx| = s * |w_int - x_int|  (u16 ints)
//   sum|.| = s * (W_SUM[f] + X_SUM[win] - 2*sum min(w_int, x_int))
// min via min.u16x2 (2 channels packed), accumulate via dp2a -> 1 instr/elem.
// ---------------------------------------------------------------------------

#define N_BATCH 4
#define C_IN    64
#define HW      28
#define F_OUT   64
#define KDIM    576
#define QX_MAX  65535.0f
#define QW_MAX  255.0f

#define MMB     32
#define SLICES  4
#define TPS     112
#define THREADS (SLICES*TPS)  // 448

__device__ float g_bmin[MMB];
__device__ float g_bmax[MMB];
__device__ float g_qw[KDIM * F_OUT];   // layout [k][f], dequantized floats

__device__ __forceinline__ unsigned minu2(unsigned a, unsigned b) {
    unsigned r;
    asm("min.u16x2 %0, %1, %2;" : "=r"(r) : "r"(a), "r"(b));
    return r;
}
#define DPB 0x00000101u   // dp2a byte pair (1,1): sums both u16 halves

// ---------------------------------------------------------------------------
// k_prep: blocks 0,1 -> W quant (coalesced transpose write to g_qw[k][f])
//         blocks 2..33 -> x min/max partials
// ---------------------------------------------------------------------------
#define PREP_SMEM (32 * 577 * 4)

__global__ void __launch_bounds__(1024, 1) k_prep(const float* __restrict__ W,
                                                  const float4* __restrict__ x,
                                                  int n4) {
    extern __shared__ float sq[];   // [32][577]
    const int tid = threadIdx.x;

    if (blockIdx.x >= 2) {
        int bid    = blockIdx.x - 2;
        int idx    = bid * 1024 + tid;
        int stride = MMB * 1024;
        float mn = 1e30f, mx = -1e30f;
        for (int i = idx; i < n4; i += stride) {
            float4 v = x[i];
            mn = fminf(fminf(fminf(mn, v.x), v.y), fminf(v.z, v.w));
            mx = fmaxf(fmaxf(fmaxf(mx, v.x), v.y), fmaxf(v.z, v.w));
        }
        #pragma unroll
        for (int o = 16; o > 0; o >>= 1) {
            mn = fminf(mn, __shfl_xor_sync(0xffffffffu, mn, o));
            mx = fmaxf(mx, __shfl_xor_sync(0xffffffffu, mx, o));
        }
        __shared__ float smn[32], smx[32];
        int warp = tid >> 5, lane = tid & 31;
        if (lane == 0) { smn[warp] = mn; smx[warp] = mx; }
        __syncthreads();
        if (warp == 0) {
            mn = smn[lane];
            mx = smx[lane];
            #pragma unroll
            for (int o = 16; o > 0; o >>= 1) {
                mn = fminf(mn, __shfl_xor_sync(0xffffffffu, mn, o));
                mx = fmaxf(mx, __shfl_xor_sync(0xffffffffu, mx, o));
            }
            if (lane == 0) { g_bmin[bid] = mn; g_bmax[bid] = mx; }
        }
        return;
    }

    const int warp = tid >> 5;
    const int lane = tid & 31;
    const int f    = blockIdx.x * 32 + warp;

    const float* wf = W + f * KDIM;
    float v[18];
    float mn = 1e30f, mx = -1e30f;
    #pragma unroll
    for (int t = 0; t < 18; ++t) {
        v[t] = wf[lane + t * 32];
        mn = fminf(mn, v[t]);
        mx = fmaxf(mx, v[t]);
    }
    #pragma unroll
    for (int o = 16; o > 0; o >>= 1) {
        mn = fminf(mn, __shfl_xor_sync(0xffffffffu, mn, o));
        mx = fmaxf(mx, __shfl_xor_sync(0xffffffffu, mx, o));
    }
    float scale = fmaxf(__fdiv_rn(mx - mn, QW_MAX), 1e-12f);
    float zp    = rintf(__fdiv_rn(-mn, scale));
    #pragma unroll
    for (int t = 0; t < 18; ++t) {
        float q = fminf(fmaxf(rintf(__fdiv_rn(v[t], scale)) + zp, 0.0f), QW_MAX);
        sq[warp * 577 + lane + t * 32] = (q - zp) * scale;
    }
    __syncthreads();

    const int j  = tid & 31;
    const int kk = tid >> 5;
    const int f0 = blockIdx.x * 32;
    #pragma unroll
    for (int p = 0; p < 18; ++p) {
        int k = p * 32 + kk;
        g_qw[k * F_OUT + f0 + j] = sq[j * 577 + k];
    }
}

// ---------------------------------------------------------------------------
// k_main: integer adder-conv. grid (28 ho, 4 n), 448 threads.
// smem (u32 units):
//   swi  [288][64]  u16x2 w pairs (c, c+32)      18432
//   sxi  [32][3][32] u16x2 x pairs               3072
//   red  uint4[896] reduction                    3584
//   wpart[7][64], wsum[64], rpart[30][8], rs[30], sprm[2]
// ---------------------------------------------------------------------------
#define SWI_OFF   0
#define SXI_OFF   18432
#define RED_OFF   21504
#define WPART_OFF 25088
#define WSUM_OFF  25536
#define RPART_OFF 25600
#define RS_OFF    25840
#define SPRM_OFF  25872
#define SMEM_U32  25876
#define SMEM_BYTES (SMEM_U32 * 4)

__global__ void __launch_bounds__(THREADS, 1) k_main(const float* __restrict__ x,
                                                     float* __restrict__ out) {
    const int ho  = blockIdx.x;
    const int n   = blockIdx.y;
    const int tid = threadIdx.x;

    extern __shared__ unsigned smem[];
    unsigned* swi   = smem + SWI_OFF;
    unsigned* sxi   = smem + SXI_OFF;
    uint4*    red   = (uint4*)(smem + RED_OFF);
    unsigned* wpart = smem + WPART_OFF;
    unsigned* wsum  = smem + WSUM_OFF;
    unsigned* rpart = smem + RPART_OFF;
    unsigned* rs    = smem + RS_OFF;
    float*    sprm  = (float*)(smem + SPRM_OFF);

    // warp 0: finalize activation quant params from 32 partials
    if (tid < 32) {
        float mn = g_bmin[tid];
        float mx = g_bmax[tid];
        #pragma unroll
        for (int o = 16; o > 0; o >>= 1) {
            mn = fminf(mn, __shfl_xor_sync(0xffffffffu, mn, o));
            mx = fmaxf(mx, __shfl_xor_sync(0xffffffffu, mx, o));
        }
        if (tid == 0) {
            float scale = fmaxf(__fdiv_rn(mx - mn, QX_MAX), 1e-12f);
            sprm[0] = scale;
            sprm[1] = rintf(__fdiv_rn(-mn, scale));
        }
    }
    __syncthreads();

    const float s   = sprm[0];
    const float zp  = sprm[1];
    const float invs = __fdiv_rn(1.0f, s);

    // stage W: re-grid dequantized qw onto the global x grid, pack (c, c+32)
    for (int idx = tid; idx < 18432; idx += THREADS) {
        float wlo = g_qw[idx];               // k = idx>>6, f = idx&63
        float whi = g_qw[idx + 288 * 64];    // channel c+32, same (i,j), same f
        float qlo = fminf(fmaxf(rintf(wlo * invs) + zp, 0.0f), 65535.0f);
        float qhi = fminf(fmaxf(rintf(whi * invs) + zp, 0.0f), 65535.0f);
        swi[idx] = (unsigned)qlo | ((unsigned)qhi << 16);
    }

    // stage x: quantize to grid indices, pack (c, c+32); padding -> zp index
    const unsigned zpu = (unsigned)zp;
    for (int idx = tid; idx < 2880; idx += THREADS) {
        int c   = idx / 90;
        int rem = idx - c * 90;
        int i   = rem / 30;
        int col = rem - i * 30;
        int h   = ho + i - 1;
        int w   = col - 1;
        unsigned vlo = zpu, vhi = zpu;
        if ((unsigned)h < (unsigned)HW && (unsigned)w < (unsigned)HW) {
            float a = x[((n * C_IN + c) * HW + h) * HW + w];
            float b = x[((n * C_IN + c + 32) * HW + h) * HW + w];
            vlo = (unsigned)fminf(fmaxf(rintf(__fdiv_rn(a, s)) + zp, 0.0f), QX_MAX);
            vhi = (unsigned)fminf(fmaxf(rintf(__fdiv_rn(b, s)) + zp, 0.0f), QX_MAX);
        }
        sxi[c * 96 + i * 32 + col] = vlo | (vhi << 16);
    }
    // pad columns 30,31 (never read by the window, keep deterministic)
    for (int idx = tid; idx < 192; idx += THREADS) {
        int c = idx / 6;
        int rem = idx - c * 6;
        int i = rem >> 1;
        int col = 30 + (rem & 1);
        sxi[c * 96 + i * 32 + col] = 0;
    }
    __syncthreads();

    // partial sums for corrections (read staged data; finalized after mainloop)
    {   // W_SUM partials: f = tid&63, p = tid>>6 in 0..6 over k-pair ranges
        int f  = tid & 63;
        int p  = tid >> 6;
        int k0 = p * 42;
        int k1 = (k0 + 42 < 288) ? k0 + 42 : 288;
        unsigned ssum = 0;
        for (int k = k0; k < k1; ++k)
            ssum = __dp2a_lo(swi[k * 64 + f], DPB, ssum);
        wpart[p * 64 + f] = ssum;
    }
    if (tid < 240) {   // x column-sum partials: col = tid/8, p = tid&7
        int col = tid >> 3;
        int p   = tid & 7;
        unsigned ssum = 0;
        #pragma unroll
        for (int cc = 0; cc < 4; ++cc)
            #pragma unroll
            for (int i = 0; i < 3; ++i)
                ssum = __dp2a_lo(sxi[(p * 4 + cc) * 96 + i * 32 + col], DPB, ssum);
        rpart[col * 8 + p] = ssum;
    }

    // ---- main loop ----
    const int slice = tid / TPS;          // 0..3
    const int t     = tid - slice * TPS;  // 0..111
    const int fgrp  = t & 15;
    const int wog   = t >> 4;             // 0..6
    const int f0    = fgrp * 4;
    const int wo0   = wog * 4;
    const int cp0   = slice * 8;          // 8 channel-pairs per slice

    unsigned acc[4][4];
    #pragma unroll
    for (int a = 0; a < 4; ++a)
        #pragma unroll
        for (int b = 0; b < 4; ++b) acc[a][b] = 0u;

    const unsigned* xrow = sxi + cp0 * 96;
    const unsigned* wrow = swi + cp0 * 9 * 64 + f0;

    #pragma unroll 2
    for (int cp = 0; cp < 8; ++cp) {
        #pragma unroll
        for (int i = 0; i < 3; ++i) {
            const unsigned* xr = xrow + i * 32 + wo0;
            uint4 xa = *(const uint4*)xr;
            uint2 xb = *(const uint2*)(xr + 4);
            unsigned xs[6] = { xa.x, xa.y, xa.z, xa.w, xb.x, xb.y };
            #pragma unroll
            for (int j = 0; j < 3; ++j) {
                uint4 w4 = *(const uint4*)(wrow + (i * 3 + j) * 64);
                #pragma unroll
                for (int k = 0; k < 4; ++k) {
                    unsigned xv = xs[j + k];
                    acc[0][k] = __dp2a_lo(minu2(w4.x, xv), DPB, acc[0][k]);
                    acc[1][k] = __dp2a_lo(minu2(w4.y, xv), DPB, acc[1][k]);
                    acc[2][k] = __dp2a_lo(minu2(w4.z, xv), DPB, acc[2][k]);
                    acc[3][k] = __dp2a_lo(minu2(w4.w, xv), DPB, acc[3][k]);
                }
            }
        }
        xrow += 96;
        wrow += 9 * 64;
    }

    uint4 va[4];
    #pragma unroll
    for (int fl = 0; fl < 4; ++fl)
        va[fl] = make_uint4(acc[fl][0], acc[fl][1], acc[fl][2], acc[fl][3]);

#define RSLOT(sl, fl) red[(((sl) * TPS + t) << 2) + (fl)]
#define RADD(sl)                                                  \
    { _Pragma("unroll") for (int fl = 0; fl < 4; ++fl) {          \
        uint4 o = RSLOT(sl, fl);                                  \
        va[fl].x += o.x; va[fl].y += o.y;                         \
        va[fl].z += o.z; va[fl].w += o.w; } }
#define RSTORE(sl)                                                \
    { _Pragma("unroll") for (int fl = 0; fl < 4; ++fl) RSLOT(sl, fl) = va[fl]; }

    // stage 1 of reduce + correction finalize (disjoint thread ranges)
    if (slice >= 2) RSTORE(slice - 2);
    if (tid < 30) {
        unsigned ssum = 0;
        #pragma unroll
        for (int p = 0; p < 8; ++p) ssum += rpart[tid * 8 + p];
        rs[tid] = ssum;
    } else if (tid >= 64 && tid < 128) {
        int f = tid - 64;
        unsigned ssum = 0;
        #pragma unroll
        for (int p = 0; p < 7; ++p) ssum += wpart[p * 64 + f];
        wsum[f] = ssum;
    }
    __syncthreads();
    if (slice < 2) RADD(slice);
    __syncthreads();
    if (slice == 1) RSTORE(0);
    __syncthreads();
    if (slice == 0) {
        RADD(0);
        int xsum[4];
        #pragma unroll
        for (int k = 0; k < 4; ++k)
            xsum[k] = (int)(rs[wo0 + k] + rs[wo0 + k + 1] + rs[wo0 + k + 2]);
        float* op = out + ((n * F_OUT + f0) * HW + ho) * HW + wo0;
        #pragma unroll
        for (int fl = 0; fl < 4; ++fl) {
            int ws = (int)wsum[f0 + fl];
            float4 o;
            o.x = s * (float)(2 * (int)va[fl].x - ws - xsum[0]);
            o.y = s * (float)(2 * (int)va[fl].y - ws - xsum[1]);
            o.z = s * (float)(2 * (int)va[fl].z - ws - xsum[2]);
            o.w = s * (float)(2 * (int)va[fl].w - ws - xsum[3]);
            *(float4*)(op + fl * HW * HW) = o;
        }
    }
#undef RSLOT
#undef RADD
#undef RSTORE
}

extern "C" void kernel_launch(void* const* d_in, const int* in_sizes, int n_in,
                              void* d_out, int out_size) {
    const float* x = (const float*)d_in[0];
    const float* W = (const float*)d_in[1];
    float* out = (float*)d_out;

    cudaFuncSetAttribute(k_prep, cudaFuncAttributeMaxDynamicSharedMemorySize,
                         PREP_SMEM);
    cudaFuncSetAttribute(k_main, cudaFuncAttributeMaxDynamicSharedMemorySize,
                         SMEM_BYTES);

    k_prep<<<MMB + 2, 1024, PREP_SMEM>>>(W, (const float4*)x,
                                         (N_BATCH * C_IN * HW * HW) / 4);
    dim3 grid(HW, N_BATCH);
    k_main<<<grid, THREADS, SMEM_BYTES>>>(x, out);
}

// round 6
// speedup vs baseline: 1.8875x; 1.1597x over previous
#include <cuda_runtime.h>
#include <cstdint>

// ---------------------------------------------------------------------------
// Quan_adder2d: fake-quant(x, 16b global) ; fake-quant(W, 8b per-out-channel)
// out[n,f,ho,wo] = -sum_{c,i,j} | qw[f,c,i,j] - qx[n,c,ho+i-1,wo+j-1] |
// Integer formulation on the global 16-bit x grid:
//   sum|.| = s * (W_SUM[f] + X_SUM[win] - 2*sum min(w_int, x_int))
// min.u16x2 (2 channels packed) + dp2a accumulate -> 1 instr/elem.
// ---------------------------------------------------------------------------

#define N_BATCH 4
#define C_IN    64
#define HW      28
#define F_OUT   64
#define KDIM    576
#define QX_MAX  65535.0f
#define QW_MAX  255.0f

#define MMB     32
#define SLICES  8
#define CPP     4             // channel-pairs per slice (8*4 = 32 pairs)
#define TPS     112
#define THREADS (SLICES*TPS)  // 896
#define NWPART  14

__device__ float g_bmin[MMB];
__device__ float g_bmax[MMB];
__device__ float g_qw[KDIM * F_OUT];   // layout [k][f], dequantized floats

__device__ __forceinline__ unsigned minu2(unsigned a, unsigned b) {
    unsigned r;
    asm("min.u16x2 %0, %1, %2;" : "=r"(r) : "r"(a), "r"(b));
    return r;
}
#define DPB 0x00000101u   // dp2a byte pair (1,1): sums both u16 halves

// ---------------------------------------------------------------------------
// k_prep: blocks 0,1 -> W quant (coalesced transpose write to g_qw[k][f])
//         blocks 2..33 -> x min/max partials
// ---------------------------------------------------------------------------
#define PREP_SMEM (32 * 577 * 4)

__global__ void __launch_bounds__(1024, 1) k_prep(const float* __restrict__ W,
                                                  const float4* __restrict__ x,
                                                  int n4) {
    extern __shared__ float sq[];   // [32][577]
    const int tid = threadIdx.x;

    if (blockIdx.x >= 2) {
        int bid    = blockIdx.x - 2;
        int idx    = bid * 1024 + tid;
        int stride = MMB * 1024;
        float mn = 1e30f, mx = -1e30f;
        for (int i = idx; i < n4; i += stride) {
            float4 v = x[i];
            mn = fminf(fminf(fminf(mn, v.x), v.y), fminf(v.z, v.w));
            mx = fmaxf(fmaxf(fmaxf(mx, v.x), v.y), fmaxf(v.z, v.w));
        }
        #pragma unroll
        for (int o = 16; o > 0; o >>= 1) {
            mn = fminf(mn, __shfl_xor_sync(0xffffffffu, mn, o));
            mx = fmaxf(mx, __shfl_xor_sync(0xffffffffu, mx, o));
        }
        __shared__ float smn[32], smx[32];
        int warp = tid >> 5, lane = tid & 31;
        if (lane == 0) { smn[warp] = mn; smx[warp] = mx; }
        __syncthreads();
        if (warp == 0) {
            mn = smn[lane];
            mx = smx[lane];
            #pragma unroll
            for (int o = 16; o > 0; o >>= 1) {
                mn = fminf(mn, __shfl_xor_sync(0xffffffffu, mn, o));
                mx = fmaxf(mx, __shfl_xor_sync(0xffffffffu, mx, o));
            }
            if (lane == 0) { g_bmin[bid] = mn; g_bmax[bid] = mx; }
        }
        return;
    }

    const int warp = tid >> 5;
    const int lane = tid & 31;
    const int f    = blockIdx.x * 32 + warp;

    const float* wf = W + f * KDIM;
    float v[18];
    float mn = 1e30f, mx = -1e30f;
    #pragma unroll
    for (int t = 0; t < 18; ++t) {
        v[t] = wf[lane + t * 32];
        mn = fminf(mn, v[t]);
        mx = fmaxf(mx, v[t]);
    }
    #pragma unroll
    for (int o = 16; o > 0; o >>= 1) {
        mn = fminf(mn, __shfl_xor_sync(0xffffffffu, mn, o));
        mx = fmaxf(mx, __shfl_xor_sync(0xffffffffu, mx, o));
    }
    float scale = fmaxf(__fdiv_rn(mx - mn, QW_MAX), 1e-12f);
    float zp    = rintf(__fdiv_rn(-mn, scale));
    #pragma unroll
    for (int t = 0; t < 18; ++t) {
        float q = fminf(fmaxf(rintf(__fdiv_rn(v[t], scale)) + zp, 0.0f), QW_MAX);
        sq[warp * 577 + lane + t * 32] = (q - zp) * scale;
    }
    __syncthreads();

    const int j  = tid & 31;
    const int kk = tid >> 5;
    const int f0 = blockIdx.x * 32;
    #pragma unroll
    for (int p = 0; p < 18; ++p) {
        int k = p * 32 + kk;
        g_qw[k * F_OUT + f0 + j] = sq[j * 577 + k];
    }
}

// ---------------------------------------------------------------------------
// k_main: integer adder-conv. grid (28 ho, 4 n), 896 threads = 8 slices x 112
// ---------------------------------------------------------------------------
#define SWI_OFF   0                    // [288][64] u16x2 w pairs
#define SXI_OFF   18432                // [32][3][32] u16x2 x pairs
#define RED_OFF   21504                // 1792 uint4 = 7168 u32
#define WPART_OFF 28672                // [14][64]
#define WSUM_OFF  29568                // [64]
#define RPART_OFF 29632                // [30][8]
#define RS_OFF    29872                // [30]
#define SPRM_OFF  29902                // [2]
#define SMEM_U32  29904
#define SMEM_BYTES (SMEM_U32 * 4)      // 119616

__global__ void __launch_bounds__(THREADS, 1) k_main(const float* __restrict__ x,
                                                     float* __restrict__ out) {
    const int ho  = blockIdx.x;
    const int n   = blockIdx.y;
    const int tid = threadIdx.x;

    extern __shared__ unsigned smem[];
    unsigned* swi   = smem + SWI_OFF;
    unsigned* sxi   = smem + SXI_OFF;
    uint4*    red   = (uint4*)(smem + RED_OFF);
    unsigned* wpart = smem + WPART_OFF;
    unsigned* wsum  = smem + WSUM_OFF;
    unsigned* rpart = smem + RPART_OFF;
    unsigned* rs    = smem + RS_OFF;
    float*    sprm  = (float*)(smem + SPRM_OFF);

    // warp 0: finalize activation quant params from 32 partials
    if (tid < 32) {
        float mn = g_bmin[tid];
        float mx = g_bmax[tid];
        #pragma unroll
        for (int o = 16; o > 0; o >>= 1) {
            mn = fminf(mn, __shfl_xor_sync(0xffffffffu, mn, o));
            mx = fmaxf(mx, __shfl_xor_sync(0xffffffffu, mx, o));
        }
        if (tid == 0) {
            float scale = fmaxf(__fdiv_rn(mx - mn, QX_MAX), 1e-12f);
            sprm[0] = scale;
            sprm[1] = rintf(__fdiv_rn(-mn, scale));
        }
    }
    __syncthreads();

    const float s    = sprm[0];
    const float zp   = sprm[1];
    const float invs = __fdiv_rn(1.0f, s);

    // stage W: re-grid dequantized qw onto the global x grid, pack (c, c+32)
    for (int idx = tid; idx < 18432; idx += THREADS) {
        float wlo = g_qw[idx];               // k = idx>>6, f = idx&63
        float whi = g_qw[idx + 288 * 64];    // channel c+32, same (i,j,f)
        float qlo = fminf(fmaxf(rintf(wlo * invs) + zp, 0.0f), 65535.0f);
        float qhi = fminf(fmaxf(rintf(whi * invs) + zp, 0.0f), 65535.0f);
        swi[idx] = (unsigned)qlo | ((unsigned)qhi << 16);
    }

    // stage x: quantize to grid indices, pack (c, c+32); padding -> zp index
    const unsigned zpu = (unsigned)zp;
    for (int idx = tid; idx < 2880; idx += THREADS) {
        int c   = idx / 90;
        int rem = idx - c * 90;
        int i   = rem / 30;
        int col = rem - i * 30;
        int h   = ho + i - 1;
        int w   = col - 1;
        unsigned vlo = zpu, vhi = zpu;
        if ((unsigned)h < (unsigned)HW && (unsigned)w < (unsigned)HW) {
            float a = x[((n * C_IN + c) * HW + h) * HW + w];
            float b = x[((n * C_IN + c + 32) * HW + h) * HW + w];
            vlo = (unsigned)fminf(fmaxf(rintf(__fdiv_rn(a, s)) + zp, 0.0f), QX_MAX);
            vhi = (unsigned)fminf(fmaxf(rintf(__fdiv_rn(b, s)) + zp, 0.0f), QX_MAX);
        }
        sxi[c * 96 + i * 32 + col] = vlo | (vhi << 16);
    }
    for (int idx = tid; idx < 192; idx += THREADS) {
        int c = idx / 6;
        int rem = idx - c * 6;
        int i = rem >> 1;
        int col = 30 + (rem & 1);
        sxi[c * 96 + i * 32 + col] = 0;
    }
    __syncthreads();

    // correction partials
    if (tid < NWPART * 64) {   // W_SUM partials: f = tid&63, p = tid>>6
        int f  = tid & 63;
        int p  = tid >> 6;
        int k0 = p * 21;
        int k1 = (k0 + 21 < 288) ? k0 + 21 : 288;
        unsigned ssum = 0;
        for (int k = k0; k < k1; ++k)
            ssum = __dp2a_lo(swi[k * 64 + f], DPB, ssum);
        wpart[p * 64 + f] = ssum;
    }
    if (tid < 240) {   // x column-sum partials: col = tid/8, p = tid&7
        int col = tid >> 3;
        int p   = tid & 7;
        unsigned ssum = 0;
        #pragma unroll
        for (int cc = 0; cc < 4; ++cc)
            #pragma unroll
            for (int i = 0; i < 3; ++i)
                ssum = __dp2a_lo(sxi[(p * 4 + cc) * 96 + i * 32 + col], DPB, ssum);
        rpart[col * 8 + p] = ssum;
    }

    // ---- main loop ----
    const int slice = tid / TPS;          // 0..7
    const int t     = tid - slice * TPS;  // 0..111
    const int fgrp  = t & 15;
    const int wog   = t >> 4;             // 0..6
    const int f0    = fgrp * 4;
    const int wo0   = wog * 4;
    const int cp0   = slice * CPP;        // 4 channel-pairs per slice

    unsigned acc[4][4];
    #pragma unroll
    for (int a = 0; a < 4; ++a)
        #pragma unroll
        for (int b = 0; b < 4; ++b) acc[a][b] = 0u;

    const unsigned* xrow = sxi + cp0 * 96;
    const unsigned* wrow = swi + cp0 * 9 * 64 + f0;

    #pragma unroll
    for (int cp = 0; cp < CPP; ++cp) {
        #pragma unroll
        for (int i = 0; i < 3; ++i) {
            // prefetch all 3 w vectors and the x window for this i
            uint4 wp0 = *(const uint4*)(wrow + (i * 3 + 0) * 64);
            uint4 wp1 = *(const uint4*)(wrow + (i * 3 + 1) * 64);
            uint4 wp2 = *(const uint4*)(wrow + (i * 3 + 2) * 64);
            const unsigned* xr = xrow + i * 32 + wo0;
            uint4 xa = *(const uint4*)xr;
            uint2 xb = *(const uint2*)(xr + 4);
            unsigned xs[6] = { xa.x, xa.y, xa.z, xa.w, xb.x, xb.y };
            #pragma unroll
            for (int k = 0; k < 4; ++k) {
                unsigned x0 = xs[k], x1 = xs[k + 1], x2 = xs[k + 2];
                acc[0][k] = __dp2a_lo(minu2(wp0.x, x0), DPB, acc[0][k]);
                acc[1][k] = __dp2a_lo(minu2(wp0.y, x0), DPB, acc[1][k]);
                acc[2][k] = __dp2a_lo(minu2(wp0.z, x0), DPB, acc[2][k]);
                acc[3][k] = __dp2a_lo(minu2(wp0.w, x0), DPB, acc[3][k]);
                acc[0][k] = __dp2a_lo(minu2(wp1.x, x1), DPB, acc[0][k]);
                acc[1][k] = __dp2a_lo(minu2(wp1.y, x1), DPB, acc[1][k]);
                acc[2][k] = __dp2a_lo(minu2(wp1.z, x1), DPB, acc[2][k]);
                acc[3][k] = __dp2a_lo(minu2(wp1.w, x1), DPB, acc[3][k]);
                acc[0][k] = __dp2a_lo(minu2(wp2.x, x2), DPB, acc[0][k]);
                acc[1][k] = __dp2a_lo(minu2(wp2.y, x2), DPB, acc[1][k]);
                acc[2][k] = __dp2a_lo(minu2(wp2.z, x2), DPB, acc[2][k]);
                acc[3][k] = __dp2a_lo(minu2(wp2.w, x2), DPB, acc[3][k]);
            }
        }
        xrow += 96;
        wrow += 9 * 64;
    }

    uint4 va[4];
    #pragma unroll
    for (int fl = 0; fl < 4; ++fl)
        va[fl] = make_uint4(acc[fl][0], acc[fl][1], acc[fl][2], acc[fl][3]);

#define RSLOT(sl, fl) red[(((sl) * TPS + t) << 2) + (fl)]
#define RADD(sl)                                                  \
    { _Pragma("unroll") for (int fl = 0; fl < 4; ++fl) {          \
        uint4 o = RSLOT(sl, fl);                                  \
        va[fl].x += o.x; va[fl].y += o.y;                         \
        va[fl].z += o.z; va[fl].w += o.w; } }
#define RSTORE(sl)                                                \
    { _Pragma("unroll") for (int fl = 0; fl < 4; ++fl) RSLOT(sl, fl) = va[fl]; }

    // 8 -> 4 (corrections finalized in parallel by low slices)
    if (slice >= 4) RSTORE(slice - 4);
    if (tid < 30) {
        unsigned ssum = 0;
        #pragma unroll
        for (int p = 0; p < 8; ++p) ssum += rpart[tid * 8 + p];
        rs[tid] = ssum;
    } else if (tid >= 64 && tid < 128) {
        int f = tid - 64;
        unsigned ssum = 0;
        #pragma unroll
        for (int p = 0; p < NWPART; ++p) ssum += wpart[p * 64 + f];
        wsum[f] = ssum;
    }
    __syncthreads();
    if (slice < 4) RADD(slice);
    __syncthreads();
    // 4 -> 2
    if (slice == 2 || slice == 3) RSTORE(slice - 2);
    __syncthreads();
    if (slice < 2) RADD(slice);
    __syncthreads();
    // 2 -> 1
    if (slice == 1) RSTORE(0);
    __syncthreads();
    if (slice == 0) {
        RADD(0);
        int xsum[4];
        #pragma unroll
        for (int k = 0; k < 4; ++k)
            xsum[k] = (int)(rs[wo0 + k] + rs[wo0 + k + 1] + rs[wo0 + k + 2]);
        float* op = out + ((n * F_OUT + f0) * HW + ho) * HW + wo0;
        #pragma unroll
        for (int fl = 0; fl < 4; ++fl) {
            int ws = (int)wsum[f0 + fl];
            float4 o;
            o.x = s * (float)(2 * (int)va[fl].x - ws - xsum[0]);
            o.y = s * (float)(2 * (int)va[fl].y - ws - xsum[1]);
            o.z = s * (float)(2 * (int)va[fl].z - ws - xsum[2]);
            o.w = s * (float)(2 * (int)va[fl].w - ws - xsum[3]);
            *(float4*)(op + fl * HW * HW) = o;
        }
    }
#undef RSLOT
#undef RADD
#undef RSTORE
}

extern "C" void kernel_launch(void* const* d_in, const int* in_sizes, int n_in,
                              void* d_out, int out_size) {
    const float* x = (const float*)d_in[0];
    const float* W = (const float*)d_in[1];
    float* out = (float*)d_out;

    cudaFuncSetAttribute(k_prep, cudaFuncAttributeMaxDynamicSharedMemorySize,
                         PREP_SMEM);
    cudaFuncSetAttribute(k_main, cudaFuncAttributeMaxDynamicSharedMemorySize,
                         SMEM_BYTES);

    k_prep<<<MMB + 2, 1024, PREP_SMEM>>>(W, (const float4*)x,
                                         (N_BATCH * C_IN * HW * HW) / 4);
    dim3 grid(HW, N_BATCH);
    k_main<<<grid, THREADS, SMEM_BYTES>>>(x, out);
}